// round 15
// baseline (speedup 1.0000x reference)
#include <cuda_runtime.h>
#include <cuda_fp16.h>
#include <cstdint>

// Varlen causal GQA flash attention — round 15.
// = R14 plus:
//  * REAL SMSP phase stagger: hA = (wid>>2)&1 (SMSP pairs are (i, i+4), the
//    R14 wid&1 stagger left partners in phase).
//  * Mask-free softmax fast path for warps fully below the causal diagonal.

#define TQ 128
#define TKS 128
#define TK 64
#define DH 128
#define NT 256
#define QSTRIDE 4096
#define KSTRIDE 1024
#define PADH 136

#define K_ST_HALVES (TKS * PADH)
#define STAGE_HALVES (2 * K_ST_HALVES)
#define STAGE_BYTES (STAGE_HALVES * 2)
#define NSTAGE 3
#define SMEM_BYTES (NSTAGE * STAGE_BYTES)  // 208896

#define CAP_TOK 8192
__device__ __half g_kh[CAP_TOK * KSTRIDE];
__device__ __half g_vh[CAP_TOK * KSTRIDE];

static __device__ __forceinline__ uint32_t smem_u32(const void* p) {
    uint32_t a;
    asm("{ .reg .u64 t; cvta.to.shared.u64 t, %1; cvt.u32.u64 %0, t; }" : "=r"(a) : "l"(p));
    return a;
}
static __device__ __forceinline__ uint32_t pack_h2(float lo, float hi) {
    uint32_t u;
    asm("cvt.rn.f16x2.f32 %0, %1, %2;" : "=r"(u) : "f"(hi), "f"(lo));
    return u;
}
static __device__ __forceinline__ float exp2f_fast(float x) {
    float y; asm("ex2.approx.ftz.f32 %0, %1;" : "=f"(y) : "f"(x)); return y;
}
static __device__ __forceinline__ void mma_f16(float c[4], const uint32_t a[4],
                                               uint32_t b0, uint32_t b1) {
    asm("mma.sync.aligned.m16n8k16.row.col.f32.f16.f16.f32 "
        "{%0,%1,%2,%3}, {%4,%5,%6,%7}, {%8,%9}, {%0,%1,%2,%3};"
        : "+f"(c[0]), "+f"(c[1]), "+f"(c[2]), "+f"(c[3])
        : "r"(a[0]), "r"(a[1]), "r"(a[2]), "r"(a[3]), "r"(b0), "r"(b1));
}
static __device__ __forceinline__ void ldsm4(uint32_t r[4], uint32_t addr) {
    asm volatile("ldmatrix.sync.aligned.m8n8.x4.shared.b16 {%0,%1,%2,%3}, [%4];"
        : "=r"(r[0]), "=r"(r[1]), "=r"(r[2]), "=r"(r[3]) : "r"(addr));
}
static __device__ __forceinline__ void ldsm4t(uint32_t r[4], uint32_t addr) {
    asm volatile("ldmatrix.sync.aligned.m8n8.x4.trans.shared.b16 {%0,%1,%2,%3}, [%4];"
        : "=r"(r[0]), "=r"(r[1]), "=r"(r[2]), "=r"(r[3]) : "r"(addr));
}
static __device__ __forceinline__ void cp16(uint32_t dst, const void* src, uint32_t n) {
    asm volatile("cp.async.cg.shared.global [%0], [%1], 16, %2;"
        :: "r"(dst), "l"(src), "r"(n) : "memory");
}
static __device__ __forceinline__ void cp_commit() {
    asm volatile("cp.async.commit_group;" ::: "memory");
}
static __device__ __forceinline__ void cp_wait1() {
    asm volatile("cp.async.wait_group 1;" ::: "memory");
}

// softmax for one 64-token half held in s[8][4]; packs PV A-fragments into pa.
static __device__ __forceinline__ void softmax_half(
    float s[8][4], uint32_t pa[4][4], int k0, int tig,
    int qrow0, int qrow1, float& lsum0, float& lsum1, bool nomask)
{
    if (nomask) {
        #pragma unroll
        for (int nt = 0; nt < 8; nt++) {
            float p0 = exp2f_fast(s[nt][0]);
            float p1 = exp2f_fast(s[nt][1]);
            float p2 = exp2f_fast(s[nt][2]);
            float p3 = exp2f_fast(s[nt][3]);
            lsum0 += p0 + p1;
            lsum1 += p2 + p3;
            const int kk = nt >> 1;
            if ((nt & 1) == 0) { pa[kk][0] = pack_h2(p0, p1); pa[kk][1] = pack_h2(p2, p3); }
            else               { pa[kk][2] = pack_h2(p0, p1); pa[kk][3] = pack_h2(p2, p3); }
        }
    } else {
        #pragma unroll
        for (int nt = 0; nt < 8; nt++) {
            const int cb = k0 + nt * 8 + tig * 2;
            float p0 = (cb     <= qrow0) ? exp2f_fast(s[nt][0]) : 0.f;
            float p1 = (cb + 1 <= qrow0) ? exp2f_fast(s[nt][1]) : 0.f;
            float p2 = (cb     <= qrow1) ? exp2f_fast(s[nt][2]) : 0.f;
            float p3 = (cb + 1 <= qrow1) ? exp2f_fast(s[nt][3]) : 0.f;
            lsum0 += p0 + p1;
            lsum1 += p2 + p3;
            const int kk = nt >> 1;
            if ((nt & 1) == 0) { pa[kk][0] = pack_h2(p0, p1); pa[kk][1] = pack_h2(p2, p3); }
            else               { pa[kk][2] = pack_h2(p0, p1); pa[kk][3] = pack_h2(p2, p3); }
        }
    }
}

// ---------------- pre-pass: fp32 K/V -> fp16 scratch ----------------
__global__ void cvt_kv_kernel(const float* __restrict__ k, const float* __restrict__ v,
                              int n8)
{
    for (int i = blockIdx.x * blockDim.x + threadIdx.x; i < n8;
         i += gridDim.x * blockDim.x) {
        const float4* kp = (const float4*)(k + (size_t)i * 8);
        const float4* vp = (const float4*)(v + (size_t)i * 8);
        float4 k0 = kp[0], k1 = kp[1];
        float4 v0 = vp[0], v1 = vp[1];
        uint4 ko, vo;
        ko.x = pack_h2(k0.x, k0.y); ko.y = pack_h2(k0.z, k0.w);
        ko.z = pack_h2(k1.x, k1.y); ko.w = pack_h2(k1.z, k1.w);
        vo.x = pack_h2(v0.x, v0.y); vo.y = pack_h2(v0.z, v0.w);
        vo.z = pack_h2(v1.x, v1.y); vo.w = pack_h2(v1.z, v1.w);
        *(uint4*)(g_kh + (size_t)i * 8) = ko;
        *(uint4*)(g_vh + (size_t)i * 8) = vo;
    }
}

// ---------------- main kernel ----------------
__global__ __launch_bounds__(NT, 1)
void fa_f16_r15_kernel(const float* __restrict__ q, const int* __restrict__ cu,
                       float* __restrict__ out, int B, int Tm1)
{
    extern __shared__ __half smem[];
    const uint32_t sbase = smem_u32(smem);

    const int head = blockIdx.x;
    int w = blockIdx.y;
    int seq = -1, q0 = 0, s0 = 0, L = 0;
    for (int si = 0; si < B; si++) {
        const int a = cu[si], b = cu[si + 1];
        const int nq = (b - a + TQ - 1) / TQ;
        if (w < nq) { seq = si; s0 = a; L = b - a; q0 = (nq - 1 - w) * TQ; break; }
        w -= nq;
    }
    if (seq < 0) return;

    const int kvh  = head >> 2;
    const int tid  = threadIdx.x;
    const int wid  = tid >> 5;
    const int lane = tid & 31;
    const int g    = lane >> 2;
    const int tig  = lane & 3;
    const int lm   = lane >> 3;
    const int lr   = lane & 7;

    const int qg_max = min(q0 + TQ - 1, L - 1);
    const int nst    = qg_max / TKS + 1;

    const __half* khead = g_kh + kvh * DH;
    const __half* vhead = g_vh + kvh * DH;

    auto issue_stage = [&](int t, int st) {
        const int k0 = t * TKS;
        const uint32_t stb = sbase + (uint32_t)(st * STAGE_BYTES);
        #pragma unroll
        for (int it = 0; it < 16; it++) {
            const int c   = tid + it * NT;
            const int kvs = c >> 11;
            const int r   = (c >> 4) & 127;
            const int c16 = c & 15;
            const int tok = k0 + r;
            const int gtok = min(s0 + tok, Tm1);
            const __half* src = (kvs ? vhead : khead)
                + (size_t)gtok * KSTRIDE + c16 * 8;
            const uint32_t dst = stb +
                (uint32_t)((kvs * K_ST_HALVES + r * PADH + c16 * 8) * 2);
            cp16(dst, src, (tok < L) ? 16u : 0u);
        }
    };

    issue_stage(0, 0); cp_commit();
    if (nst > 1) issue_stage(1, 1);
    cp_commit();

    const int qrow0 = q0 + wid * 16 + g;
    const int qrow1 = qrow0 + 8;
    const bool ok0 = qrow0 < L, ok1 = qrow1 < L;

    // ---- Q fragments directly from gmem (m16n8k16 A layout) ----
    const float scale = 0.08838834764831845f * 1.4426950408889634f; // *log2e
    uint32_t qa[8][4];
    {
        const float* p0 = q + (size_t)(s0 + min(qrow0, L - 1)) * QSTRIDE + head * DH;
        const float* p1 = q + (size_t)(s0 + min(qrow1, L - 1)) * QSTRIDE + head * DH;
        const float2 z = make_float2(0.f, 0.f);
        #pragma unroll
        for (int ks = 0; ks < 8; ks++) {
            const int c = ks * 16 + tig * 2;
            float2 v00 = ok0 ? *(const float2*)(p0 + c)     : z;
            float2 v10 = ok1 ? *(const float2*)(p1 + c)     : z;
            float2 v01 = ok0 ? *(const float2*)(p0 + c + 8) : z;
            float2 v11 = ok1 ? *(const float2*)(p1 + c + 8) : z;
            qa[ks][0] = pack_h2(v00.x * scale, v00.y * scale);
            qa[ks][1] = pack_h2(v10.x * scale, v10.y * scale);
            qa[ks][2] = pack_h2(v01.x * scale, v01.y * scale);
            qa[ks][3] = pack_h2(v11.x * scale, v11.y * scale);
        }
    }

    float o[16][4];
    #pragma unroll
    for (int nt = 0; nt < 16; nt++)
        #pragma unroll
        for (int r = 0; r < 4; r++) o[nt][r] = 0.f;
    float lsum0 = 0.f, lsum1 = 0.f;

    const int wrow_min = q0 + wid * 16;               // warp's first q row
    const int wrow_max = min(wrow_min + 15, L - 1);

    const uint32_t koff = (uint32_t)((((lm >> 1) * 8 + lr) * PADH + (lm & 1) * 8) * 2);
    const uint32_t voff = (uint32_t)((((lm & 1) * 8 + lr) * PADH + (lm >> 1) * 8) * 2);

    // SMSP pairs are (wid, wid+4): stagger halves by wid>>2 to desync partners.
    const int hA = (wid >> 2) & 1;
    const uint32_t offA = (uint32_t)(hA * TK * PADH * 2);
    const uint32_t offB = (uint32_t)((1 - hA) * TK * PADH * 2);

    for (int t = 0; t < nst; t++) {
        cp_wait1();
        __syncthreads();

        if (t + 2 < nst) issue_stage(t + 2, (t + 2) % NSTAGE);
        cp_commit();

        const uint32_t KstBase = sbase + (uint32_t)((t % NSTAGE) * STAGE_BYTES);
        const uint32_t VstBase = KstBase + (uint32_t)(K_ST_HALVES * 2);

        const int k0s  = t * TKS;
        const int cap1 = wrow_max - (k0s + TK);
        const int jmax1 = (cap1 < 0) ? 0 : min(4, (cap1 >> 4) + 1);

        float s[8][4];
        uint32_t pa[4][4];

        if (jmax1 == 4) {
            const uint32_t KstA = KstBase + offA, VstA = VstBase + offA;
            const uint32_t KstB = KstBase + offB, VstB = VstBase + offB;
            const int kA = k0s + hA * TK;
            const int kB = k0s + (1 - hA) * TK;
            const bool nomaskA = wrow_min >= kA + TK - 1;
            const bool nomaskB = wrow_min >= kB + TK - 1;

            // -- QK(hA), pipelined ring-3 --
            #pragma unroll
            for (int nt = 0; nt < 8; nt++)
                s[nt][0] = s[nt][1] = s[nt][2] = s[nt][3] = 0.f;
            {
                uint32_t br[3][4];
                ldsm4(br[0], KstA + koff);
                ldsm4(br[1], KstA + koff + (uint32_t)(16 * PADH * 2));
                #pragma unroll
                for (int st = 0; st < 32; st++) {
                    if (st + 2 < 32) {
                        const int ns = st + 2;
                        ldsm4(br[ns % 3], KstA + koff +
                              (uint32_t)(((ns & 3) * 16 * PADH + (ns >> 2) * 16) * 2));
                    }
                    const int ks = st >> 2, j = st & 3;
                    mma_f16(s[2 * j],     qa[ks], br[st % 3][0], br[st % 3][1]);
                    mma_f16(s[2 * j + 1], qa[ks], br[st % 3][2], br[st % 3][3]);
                }
            }
            softmax_half(s, pa, kA, tig, qrow0, qrow1, lsum0, lsum1, nomaskA);

            // -- FUSED: PV(hA) + QK(hB) --
            #pragma unroll
            for (int nt = 0; nt < 8; nt++)
                s[nt][0] = s[nt][1] = s[nt][2] = s[nt][3] = 0.f;
            {
                uint32_t bv[2][4], br[2][4];
                ldsm4t(bv[0], VstA + voff);
                ldsm4(br[0], KstB + koff);
                #pragma unroll
                for (int st = 0; st < 32; st++) {
                    if (st + 1 < 32) {
                        const int ns = st + 1;
                        ldsm4t(bv[ns & 1], VstA + voff +
                               (uint32_t)(((ns >> 3) * 16 * PADH + (ns & 7) * 16) * 2));
                        ldsm4(br[ns & 1], KstB + koff +
                              (uint32_t)(((ns & 3) * 16 * PADH + (ns >> 2) * 16) * 2));
                    }
                    const int kk = st >> 3, d = st & 7;
                    const int ks = st >> 2, j = st & 3;
                    mma_f16(o[2 * d],     pa[kk], bv[st & 1][0], bv[st & 1][1]);
                    mma_f16(s[2 * j],     qa[ks], br[st & 1][0], br[st & 1][1]);
                    mma_f16(o[2 * d + 1], pa[kk], bv[st & 1][2], bv[st & 1][3]);
                    mma_f16(s[2 * j + 1], qa[ks], br[st & 1][2], br[st & 1][3]);
                }
            }
            softmax_half(s, pa, kB, tig, qrow0, qrow1, lsum0, lsum1, nomaskB);

            // -- PV(hB), pipelined ring-3 --
            {
                uint32_t bv[3][4];
                ldsm4t(bv[0], VstB + voff);
                ldsm4t(bv[1], VstB + voff + 32);
                #pragma unroll
                for (int st = 0; st < 32; st++) {
                    if (st + 2 < 32) {
                        const int ns = st + 2;
                        ldsm4t(bv[ns % 3], VstB + voff +
                               (uint32_t)(((ns >> 3) * 16 * PADH + (ns & 7) * 16) * 2));
                    }
                    const int kk = st >> 3, d = st & 7;
                    mma_f16(o[2 * d],     pa[kk], bv[st % 3][0], bv[st % 3][1]);
                    mma_f16(o[2 * d + 1], pa[kk], bv[st % 3][2], bv[st % 3][3]);
                }
            }
        } else {
            // ============ sequential fallback (diagonal/capped) =============
            #pragma unroll
            for (int h = 0; h < 2; h++) {
                const int k0 = k0s + h * TK;
                const int cap  = wrow_max - k0;
                const int jmax = (cap < 0) ? 0 : min(4, (cap >> 4) + 1);
                if (jmax == 0) continue;

                const uint32_t Kst = KstBase + (uint32_t)(h * TK * PADH * 2);
                const uint32_t Vst = VstBase + (uint32_t)(h * TK * PADH * 2);

                #pragma unroll
                for (int nt = 0; nt < 8; nt++)
                    s[nt][0] = s[nt][1] = s[nt][2] = s[nt][3] = 0.f;

                #pragma unroll
                for (int ks = 0; ks < 8; ks++) {
                    #pragma unroll
                    for (int j = 0; j < 4; j++) {
                        if (j < jmax) {
                            uint32_t br[4];
                            ldsm4(br, Kst + koff +
                                  (uint32_t)((j * 16 * PADH + ks * 16) * 2));
                            mma_f16(s[2 * j],     qa[ks], br[0], br[1]);
                            mma_f16(s[2 * j + 1], qa[ks], br[2], br[3]);
                        }
                    }
                }

                #pragma unroll
                for (int nt = 0; nt < 8; nt++) {
                    if (nt < 2 * jmax) {
                        const int cb = k0 + nt * 8 + tig * 2;
                        float p0 = (cb     <= qrow0) ? exp2f_fast(s[nt][0]) : 0.f;
                        float p1 = (cb + 1 <= qrow0) ? exp2f_fast(s[nt][1]) : 0.f;
                        float p2 = (cb     <= qrow1) ? exp2f_fast(s[nt][2]) : 0.f;
                        float p3 = (cb + 1 <= qrow1) ? exp2f_fast(s[nt][3]) : 0.f;
                        lsum0 += p0 + p1;
                        lsum1 += p2 + p3;
                        const int kk = nt >> 1;
                        if ((nt & 1) == 0) { pa[kk][0] = pack_h2(p0, p1); pa[kk][1] = pack_h2(p2, p3); }
                        else               { pa[kk][2] = pack_h2(p0, p1); pa[kk][3] = pack_h2(p2, p3); }
                    }
                }

                #pragma unroll
                for (int kk = 0; kk < 4; kk++) {
                    if (kk < jmax) {
                        #pragma unroll
                        for (int d = 0; d < 8; d++) {
                            uint32_t br[4];
                            ldsm4t(br, Vst + voff +
                                   (uint32_t)((kk * 16 * PADH + d * 16) * 2));
                            mma_f16(o[2 * d],     pa[kk], br[0], br[1]);
                            mma_f16(o[2 * d + 1], pa[kk], br[2], br[3]);
                        }
                    }
                }
            }
        }
    }

    // ---- epilogue: quad-reduce l, normalize, store ----
    #pragma unroll
    for (int off = 1; off < 4; off <<= 1) {
        lsum0 += __shfl_xor_sync(0xffffffffu, lsum0, off);
        lsum1 += __shfl_xor_sync(0xffffffffu, lsum1, off);
    }
    const float inv0 = 1.0f / lsum0;
    const float inv1 = 1.0f / lsum1;

    float* ob0 = out + (size_t)(s0 + qrow0) * QSTRIDE + head * DH;
    float* ob1 = out + (size_t)(s0 + qrow1) * QSTRIDE + head * DH;
    #pragma unroll
    for (int nt = 0; nt < 16; nt++) {
        const int c = nt * 8 + tig * 2;
        if (ok0) *(float2*)(ob0 + c) = make_float2(o[nt][0] * inv0, o[nt][1] * inv0);
        if (ok1) *(float2*)(ob1 + c) = make_float2(o[nt][2] * inv1, o[nt][3] * inv1);
    }
}

extern "C" void kernel_launch(void* const* d_in, const int* in_sizes, int n_in,
                              void* d_out, int out_size)
{
    const float* q  = (const float*)d_in[0];
    const float* k  = (const float*)d_in[1];
    const float* v  = (const float*)d_in[2];
    const int*   cu = (const int*)d_in[3];

    const int T = in_sizes[0] / QSTRIDE;
    const int B = in_sizes[3] - 1;

    const int n8 = T * KSTRIDE / 8;
    cvt_kv_kernel<<<592, 256>>>(k, v, n8);

    const int wub = (T + TQ - 1) / TQ + B;

    cudaFuncSetAttribute(fa_f16_r15_kernel,
                         cudaFuncAttributeMaxDynamicSharedMemorySize, SMEM_BYTES);

    dim3 grid(32, wub);
    fa_f16_r15_kernel<<<grid, NT, SMEM_BYTES>>>(q, cu, (float*)d_out, B, T - 1);
}